// round 11
// baseline (speedup 1.0000x reference)
#include <cuda_runtime.h>

#define NN      262144          // 64^3
#define NNZ_TOT (7 * NN)
#define BS      128
#define CH      32              // batch chunk width
#define NCHUNK  (BS / CH)       // 4
#define RPW     16              // rows per warp
#define RPB     128             // rows per block (8 warps)
#define SMCAP   1280            // staged CSR entries per block (mean 896, sd 30)

// Scratch (allocation-free rule). Resident: ypT 32 MB + CSR ~15.7 MB.
__device__ float  g_ypT[(size_t)NN * CH];
__device__ int    g_cnt[NN];
__device__ int    g_off[NN + 1];
__device__ int    g_fill[NN];
__device__ int2   g_csr[NNZ_TOT];           // (col, val-bits) sorted by row
__device__ int    g_bsum[256];
__device__ double g_acc[5 * BS];

// ---- init: transpose yp chunk 0, zero g_cnt, zero g_acc
// grid = NN/32 = 8192, block = (32, 8)
__global__ void init_kernel(const float* __restrict__ yp) {
    __shared__ float tp[32][33];
    int n0 = blockIdx.x * 32;
    int tx = threadIdx.x, ty = threadIdx.y;
    int tid = ty * 32 + tx;
#pragma unroll
    for (int r = 0; r < 32; r += 8)
        tp[ty + r][tx] = __ldcs(yp + (size_t)(ty + r) * NN + n0 + tx);
    if (ty == 0) g_cnt[n0 + tx] = 0;
    if (blockIdx.x == 0)
        for (int i = tid; i < 5 * BS; i += 256) g_acc[i] = 0.0;
    __syncthreads();
#pragma unroll
    for (int r = 0; r < 32; r += 8)
        g_ypT[(size_t)(n0 + ty + r) * 32 + tx] = tp[tx][ty + r];
}

// ---- prep (chunks 1..3): transpose yp only
__global__ void prep_chunk(const float* __restrict__ yp, int b0) {
    __shared__ float tp[32][33];
    int n0 = blockIdx.x * 32;
    int tx = threadIdx.x, ty = threadIdx.y;
#pragma unroll
    for (int r = 0; r < 32; r += 8)
        tp[ty + r][tx] = __ldcs(yp + (size_t)(b0 + ty + r) * NN + n0 + tx);
    __syncthreads();
#pragma unroll
    for (int r = 0; r < 32; r += 8)
        g_ypT[(size_t)(n0 + ty + r) * 32 + tx] = tp[tx][ty + r];
}

// ------------------------------------------------------------- histogram
__global__ void hist_kernel(const int* __restrict__ rows) {
    int i = blockIdx.x * blockDim.x + threadIdx.x;
    int stride = gridDim.x * blockDim.x;
    for (; i < NNZ_TOT; i += stride)
        atomicAdd(&g_cnt[__ldcs(rows + i)], 1);
}

// ------------------------------------------------- block scan primitives
__device__ __forceinline__ int blockExclScan256(int local, int tid) {
    int lane = tid & 31, w = tid >> 5;
    int inc = local;
#pragma unroll
    for (int d = 1; d < 32; d <<= 1) {
        int n = __shfl_up_sync(0xffffffffu, inc, d);
        if (lane >= d) inc += n;
    }
    __shared__ int wsum[8];
    if (lane == 31) wsum[w] = inc;
    __syncthreads();
    if (tid == 0) {
        int run = 0;
#pragma unroll
        for (int k = 0; k < 8; k++) { int t = wsum[k]; wsum[k] = run; run += t; }
    }
    __syncthreads();
    return inc - local + wsum[w];
}

__global__ void scan_reduce_kernel() {
    int tid = threadIdx.x;
    int4 v = ((const int4*)g_cnt)[blockIdx.x * 256 + tid];
    int local = v.x + v.y + v.z + v.w;
    int lane = tid & 31, w = tid >> 5;
    int s = local;
#pragma unroll
    for (int d = 16; d > 0; d >>= 1) s += __shfl_down_sync(0xffffffffu, s, d);
    __shared__ int wsum[8];
    if (lane == 0) wsum[w] = s;
    __syncthreads();
    if (tid == 0) {
        int tot = 0;
#pragma unroll
        for (int k = 0; k < 8; k++) tot += wsum[k];
        g_bsum[blockIdx.x] = tot;
    }
}

__global__ void scan_top_kernel() {
    int tid = threadIdx.x;
    int v = g_bsum[tid];
    int e = blockExclScan256(v, tid);
    __syncthreads();
    g_bsum[tid] = e;
}

__global__ void scan_spread_kernel() {
    int tid = threadIdx.x;
    int gbase = blockIdx.x * 1024 + tid * 4;
    int4 v = ((const int4*)g_cnt)[blockIdx.x * 256 + tid];
    int local = v.x + v.y + v.z + v.w;
    int pre = blockExclScan256(local, tid);
    int o = g_bsum[blockIdx.x] + pre;
    g_off[gbase + 0] = o;  g_fill[gbase + 0] = o;  o += v.x;
    g_off[gbase + 1] = o;  g_fill[gbase + 1] = o;  o += v.y;
    g_off[gbase + 2] = o;  g_fill[gbase + 2] = o;  o += v.z;
    g_off[gbase + 3] = o;  g_fill[gbase + 3] = o;
    if (blockIdx.x == 0 && tid == 0) g_off[NN] = NNZ_TOT;
}

__global__ void fill_kernel(const float* __restrict__ vals,
                            const int* __restrict__ rows,
                            const int* __restrict__ cols) {
    int i = blockIdx.x * blockDim.x + threadIdx.x;
    int stride = gridDim.x * blockDim.x;
    for (; i < NNZ_TOT; i += stride) {
        int r = __ldcs(rows + i);
        int pos = atomicAdd(&g_fill[r], 1);
        g_csr[pos] = make_int2(__ldcs(cols + i),
                               __float_as_int(__ldcs(vals + i)));
    }
}

// ---- fused SpMV + all reductions. Block owns 128 rows; warp w owns rows
// rbase..rbase+15; lane = batch element. Block's CSR segment staged to smem
// (coalesced). Inner loop: fixed batches of 8 independent LDS->LDG pairs
// (MLP=8/lane). h lives in a register -> Yhat never materialized, no atomics.
__global__ void __launch_bounds__(256) fused_chunk(const float* __restrict__ yt,
                                                   int b0) {
    __shared__ float smT[RPB][33];       // yt tile, [row_local][batch]
    __shared__ int   smc[SMCAP + 8];
    __shared__ float smv[SMCAP + 8];
    __shared__ float red[5][8][32];
    __shared__ int   sseg[2];
    int tid  = threadIdx.x;
    int lane = tid & 31;
    int w    = tid >> 5;
    int rblk  = blockIdx.x * RPB;
    int rbase = rblk + w * RPW;

    int offv = (lane <= RPW) ? __ldg(&g_off[rbase + lane]) : 0;
    if (w == 0 && lane == 0)  sseg[0] = offv;        // g_off[rblk]
    if (w == 7 && lane == RPW) sseg[1] = offv;       // g_off[rblk+128]

    // yt tile (128 n x 32 b) transposed into smem, coalesced float4.
    {
        int j  = tid >> 3;
        int c0 = tid & 7;
        const float4* ytr = (const float4*)(yt + (size_t)(b0 + j) * NN) + blockIdx.x * 32;
#pragma unroll
        for (int pass = 0; pass < 4; pass++) {
            int n4 = pass * 8 + c0;
            float4 v = __ldcs(&ytr[n4]);
            smT[n4 * 4 + 0][j] = v.x;
            smT[n4 * 4 + 1][j] = v.y;
            smT[n4 * 4 + 2][j] = v.z;
            smT[n4 * 4 + 3][j] = v.w;
        }
    }
    __syncthreads();

    int sbeg = sseg[0];
    int seg  = sseg[1] - sbeg;
    bool fits = (seg <= SMCAP);
    if (fits) {
        for (int k = tid; k < seg; k += 256) {
            int2 cv = __ldg(&g_csr[sbeg + k]);
            smc[k] = cv.x;
            smv[k] = __int_as_float(cv.y);
        }
    }
    __syncthreads();

    float a1 = 0.f, a2 = 0.f, a3 = 0.f, a4 = 0.f, a5 = 0.f;

    if (fits) {                                 // ---------- hot path
#pragma unroll 1
        for (int i = 0; i < RPW; i++) {
            int beg = __shfl_sync(0xffffffffu, offv, i) - sbeg;
            int end = __shfl_sync(0xffffffffu, offv, i + 1) - sbeg;
            float h = 0.f;
            for (int q0 = beg; q0 < end; q0 += 8) {
#pragma unroll
                for (int k = 0; k < 8; k++) {
                    int q = q0 + k;
                    bool pr = q < end;
                    int idx = pr ? q : beg;     // in-bounds, dup line if padded
                    int   cc = smc[idx];
                    float vr = smv[idx];
                    float vv = pr ? vr : 0.f;
                    h += vv * __ldg(&g_ypT[(size_t)cc * 32 + lane]);
                }
            }
            float p = __ldg(&g_ypT[(size_t)(rbase + i) * 32 + lane]);
            float t = smT[w * RPW + i][lane];
            a1 += t * p;
            a2 += p * h;
            a3 += t * t;
            a4 += t * h;
            a5 += h * h;
        }
    } else {                                    // ---------- rare slow path
#pragma unroll 1
        for (int i = 0; i < RPW; i++) {
            int beg = __shfl_sync(0xffffffffu, offv, i);
            int end = __shfl_sync(0xffffffffu, offv, i + 1);
            float h = 0.f;
            for (int q = beg; q < end; q++) {
                int2 cv = __ldg(&g_csr[q]);
                h += __int_as_float(cv.y) * __ldg(&g_ypT[(size_t)cv.x * 32 + lane]);
            }
            float p = __ldg(&g_ypT[(size_t)(rbase + i) * 32 + lane]);
            float t = smT[w * RPW + i][lane];
            a1 += t * p;
            a2 += p * h;
            a3 += t * t;
            a4 += t * h;
            a5 += h * h;
        }
    }

    red[0][w][lane] = a1;
    red[1][w][lane] = a2;
    red[2][w][lane] = a3;
    red[3][w][lane] = a4;
    red[4][w][lane] = a5;
    __syncthreads();

    if (tid < 160) {
        int acc = tid >> 5;
        int j   = tid & 31;
        float s = 0.f;
#pragma unroll
        for (int ww = 0; ww < 8; ww++) s += red[acc][ww][j];
        atomicAdd(&g_acc[acc * BS + b0 + j], (double)s);
    }
}

// ------------------------------------------------------------ final scalar
__global__ void final_kernel(float* out) {
    int b = threadIdx.x;            // 128 threads
    double s1 = g_acc[0 * BS + b];
    double s2 = g_acc[1 * BS + b];
    double s3 = g_acc[2 * BS + b];
    double s4 = g_acc[3 * BS + b];
    double s5 = g_acc[4 * BS + b];
    double c  = s1 / s2;
    double r  = s3 - 2.0 * c * s4 + c * c * s5;
    __shared__ double sh[128];
    sh[b] = r;
    __syncthreads();
    for (int s = 64; s > 0; s >>= 1) {
        if (b < s) sh[b] += sh[b + s];
        __syncthreads();
    }
    if (b == 0) out[0] = (float)(sh[0] / (double)BS);
}

extern "C" void kernel_launch(void* const* d_in, const int* in_sizes, int n_in,
                              void* d_out, int out_size) {
    const float* yp   = (const float*)d_in[0];
    const float* yt   = (const float*)d_in[1];
    const float* vals = (const float*)d_in[2];
    const int*   rows = (const int*)d_in[3];
    const int*   cols = (const int*)d_in[4];
    float*       out  = (float*)d_out;

    // init (chunk-0 transpose + zeros), then CSR build (counting sort)
    init_kernel<<<NN / 32, dim3(32, 8)>>>(yp);
    hist_kernel<<<1184, 256>>>(rows);
    scan_reduce_kernel<<<256, 256>>>();
    scan_top_kernel<<<1, 256>>>();
    scan_spread_kernel<<<256, 256>>>();
    fill_kernel<<<1184, 256>>>(vals, rows, cols);

    for (int c = 0; c < NCHUNK; c++) {
        if (c > 0)
            prep_chunk<<<NN / 32, dim3(32, 8)>>>(yp, c * CH);
        fused_chunk<<<NN / RPB, 256>>>(yt, c * CH);
    }
    final_kernel<<<1, BS>>>(out);
}

// round 13
// speedup vs baseline: 1.0566x; 1.0566x over previous
#include <cuda_runtime.h>

#define NN      262144          // 64^3
#define NNZ_TOT (7 * NN)
#define BS      128
#define CH      32              // batch chunk width
#define NCHUNK  (BS / CH)       // 4

// Resident scratch: ypT + yhT = 64 MB, fits L2 with slack.
__device__ float  g_ypT[(size_t)NN * CH];   // y_pred chunk (N, 32)  32 MB
__device__ float  g_yhT[(size_t)NN * CH];   // Yhat  chunk (N, 32)  32 MB
__device__ double g_acc[5 * BS];            // s1..s5 per batch element

// ---- init (chunk 0): transpose yp, zero yhT, zero acc
// grid = NN/32, block = (32, 8)
__global__ void init_kernel(const float* __restrict__ yp) {
    __shared__ float tp[32][33];
    int n0 = blockIdx.x * 32;
    int tx = threadIdx.x, ty = threadIdx.y;
    int tid = ty * 32 + tx;
#pragma unroll
    for (int r = 0; r < 32; r += 8)
        tp[ty + r][tx] = __ldcs(yp + (size_t)(ty + r) * NN + n0 + tx);
    ((float4*)g_yhT)[(size_t)n0 * 8 + tid] = make_float4(0.f, 0.f, 0.f, 0.f);
    if (blockIdx.x == 0)
        for (int i = tid; i < 5 * BS; i += 256) g_acc[i] = 0.0;
    __syncthreads();
#pragma unroll
    for (int r = 0; r < 32; r += 8)
        g_ypT[(size_t)(n0 + ty + r) * 32 + tx] = tp[tx][ty + r];
}

// ---- prep (chunks 1..3): transpose yp only (yhT zeroed by reduce)
__global__ void prep_chunk(const float* __restrict__ yp, int b0) {
    __shared__ float tp[32][33];
    int n0 = blockIdx.x * 32;
    int tx = threadIdx.x, ty = threadIdx.y;
#pragma unroll
    for (int r = 0; r < 32; r += 8)
        tp[ty + r][tx] = __ldcs(yp + (size_t)(b0 + ty + r) * NN + n0 + tx);
    __syncthreads();
#pragma unroll
    for (int r = 0; r < 32; r += 8)
        g_ypT[(size_t)(n0 + ty + r) * 32 + tx] = tp[tx][ty + r];
}

// ---- per-chunk scatter: Yhat_c[:, r] += v * yp_c[:, c]   (L2-capped)
__global__ void scatter_chunk(const float* __restrict__ vals,
                              const int* __restrict__ rows,
                              const int* __restrict__ cols) {
    const float4* yp4 = (const float4*)g_ypT;
    float4*       yh4 = (float4*)g_yhT;
    int gid    = blockIdx.x * blockDim.x + threadIdx.x;
    int stride = gridDim.x * blockDim.x;
    int sub    = gid & 7;
    for (int q = gid >> 3; q < NNZ_TOT; q += (stride >> 3)) {
        int   r = __ldcs(rows + q);
        int   c = __ldcs(cols + q);
        float v = __ldcs(vals + q);
        float4 p = __ldg(&yp4[(size_t)c * 8 + sub]);
        atomicAdd(&yh4[(size_t)r * 8 + sub],
                  make_float4(v * p.x, v * p.y, v * p.z, v * p.w));
    }
}

// ---- per-chunk reduce v2 (software-pipelined): prefetch p/h (L2) into
// registers and issue yhT zero-stores BEFORE the yt DRAM tile load, so the
// two latency streams overlap. 512 threads = 16 warps; warp owns 2
// row-groups (8 rows); block covers 128 rows; grid = NN/128 = 2048.
__global__ void __launch_bounds__(512)
reduce_chunk(const float* __restrict__ yt, int b0) {
    __shared__ float smT[128][33];
    __shared__ float red[5][16][32];
    int tid  = threadIdx.x;
    int lane = tid & 31;
    int w    = tid >> 5;                          // 0..15

    const float4* yp4 = (const float4*)g_ypT;
    float4*       yh4 = (float4*)g_yhT;

    // --- phase 1: issue L2 loads + zero-stores (no sync yet)
    size_t f0 = ((size_t)blockIdx.x * 32 + w * 2) * 32 + lane;
    size_t f1 = f0 + 32;
    float4 p0 = __ldg(&yp4[f0]);
    float4 h0 = yh4[f0];
    float4 p1 = __ldg(&yp4[f1]);
    float4 h1 = yh4[f1];
    yh4[f0] = make_float4(0.f, 0.f, 0.f, 0.f);    // zero for next scatter
    yh4[f1] = make_float4(0.f, 0.f, 0.f, 0.f);

    // --- phase 2: yt tile (128 n x 32 b) transposed into smem (DRAM stream)
    {
        int j  = tid >> 4;                        // 0..31 batch row
        int c0 = tid & 15;                        // float4 col within tile
        const float4* ytr = (const float4*)(yt + (size_t)(b0 + j) * NN) + blockIdx.x * 32;
#pragma unroll
        for (int pass = 0; pass < 2; pass++) {
            int n4 = pass * 16 + c0;
            float4 v = __ldcs(&ytr[n4]);
            smT[n4 * 4 + 0][j] = v.x;
            smT[n4 * 4 + 1][j] = v.y;
            smT[n4 * 4 + 2][j] = v.z;
            smT[n4 * 4 + 3][j] = v.w;
        }
    }
    __syncthreads();

    // --- phase 3: compute. lane -> 4 batch cols j0..j0+3, row nl.
    int j0   = (lane & 7) * 4;
    int nsub = lane >> 3;

    float a1[4], a2[4], a3[4], a4[4], a5[4];
#pragma unroll
    for (int k = 0; k < 4; k++) { a1[k]=0.f; a2[k]=0.f; a3[k]=0.f; a4[k]=0.f; a5[k]=0.f; }

#pragma unroll
    for (int g = 0; g < 2; g++) {
        float4 p = g ? p1 : p0;
        float4 h = g ? h1 : h0;
        int nl = w * 8 + g * 4 + nsub;            // local n row 0..127
        float t0 = smT[nl][j0 + 0];
        float t1 = smT[nl][j0 + 1];
        float t2 = smT[nl][j0 + 2];
        float t3 = smT[nl][j0 + 3];
        a1[0] += t0 * p.x; a1[1] += t1 * p.y; a1[2] += t2 * p.z; a1[3] += t3 * p.w;
        a2[0] += p.x * h.x; a2[1] += p.y * h.y; a2[2] += p.z * h.z; a2[3] += p.w * h.w;
        a3[0] += t0 * t0;  a3[1] += t1 * t1;  a3[2] += t2 * t2;  a3[3] += t3 * t3;
        a4[0] += t0 * h.x; a4[1] += t1 * h.y; a4[2] += t2 * h.z; a4[3] += t3 * h.w;
        a5[0] += h.x * h.x; a5[1] += h.y * h.y; a5[2] += h.z * h.z; a5[3] += h.w * h.w;
    }

    // lanes {l, l+8, l+16, l+24} hold the same 4 batch columns
#pragma unroll
    for (int k = 0; k < 4; k++) {
#pragma unroll
        for (int d = 16; d >= 8; d >>= 1) {
            a1[k] += __shfl_down_sync(0xffffffffu, a1[k], d);
            a2[k] += __shfl_down_sync(0xffffffffu, a2[k], d);
            a3[k] += __shfl_down_sync(0xffffffffu, a3[k], d);
            a4[k] += __shfl_down_sync(0xffffffffu, a4[k], d);
            a5[k] += __shfl_down_sync(0xffffffffu, a5[k], d);
        }
    }

    if (lane < 8) {
#pragma unroll
        for (int k = 0; k < 4; k++) {
            red[0][w][lane * 4 + k] = a1[k];
            red[1][w][lane * 4 + k] = a2[k];
            red[2][w][lane * 4 + k] = a3[k];
            red[3][w][lane * 4 + k] = a4[k];
            red[4][w][lane * 4 + k] = a5[k];
        }
    }
    __syncthreads();

    if (tid < 160) {
        int acc = tid >> 5;
        int j   = tid & 31;
        float s = 0.f;
#pragma unroll
        for (int ww = 0; ww < 16; ww++) s += red[acc][ww][j];
        atomicAdd(&g_acc[acc * BS + b0 + j], (double)s);
    }
}

// ------------------------------------------------------------ final scalar
__global__ void final_kernel(float* out) {
    int b = threadIdx.x;            // 128 threads
    double s1 = g_acc[0 * BS + b];
    double s2 = g_acc[1 * BS + b];
    double s3 = g_acc[2 * BS + b];
    double s4 = g_acc[3 * BS + b];
    double s5 = g_acc[4 * BS + b];
    double c  = s1 / s2;
    double r  = s3 - 2.0 * c * s4 + c * c * s5;
    __shared__ double sh[128];
    sh[b] = r;
    __syncthreads();
    for (int s = 64; s > 0; s >>= 1) {
        if (b < s) sh[b] += sh[b + s];
        __syncthreads();
    }
    if (b == 0) out[0] = (float)(sh[0] / (double)BS);
}

extern "C" void kernel_launch(void* const* d_in, const int* in_sizes, int n_in,
                              void* d_out, int out_size) {
    const float* yp   = (const float*)d_in[0];
    const float* yt   = (const float*)d_in[1];
    const float* vals = (const float*)d_in[2];
    const int*   rows = (const int*)d_in[3];
    const int*   cols = (const int*)d_in[4];
    float*       out  = (float*)d_out;

    init_kernel<<<NN / 32, dim3(32, 8)>>>(yp);
    for (int c = 0; c < NCHUNK; c++) {
        if (c > 0)
            prep_chunk<<<NN / 32, dim3(32, 8)>>>(yp, c * CH);
        scatter_chunk<<<2368, 256>>>(vals, rows, cols);
        reduce_chunk<<<NN / 128, 512>>>(yt, c * CH);
    }
    final_kernel<<<1, BS>>>(out);
}

// round 14
// speedup vs baseline: 1.1879x; 1.1243x over previous
#include <cuda_runtime.h>

#define NN      262144          // 64^3
#define NNZ_TOT (7 * NN)
#define BS      128
#define CH      32              // batch chunk width
#define NCHUNK  (BS / CH)       // 4

// Resident scratch: ypT + yhT = 64 MB, fits L2 with slack.
__device__ float  g_ypT[(size_t)NN * CH];   // y_pred chunk (N, 32)  32 MB
__device__ float  g_yhT[(size_t)NN * CH];   // Yhat  chunk (N, 32)  32 MB
__device__ double g_acc[5 * BS];            // s1..s5 per batch element

// ---- init (chunk 0): transpose yp, zero yhT, zero acc
// grid = NN/32, block = (32, 8)
__global__ void init_kernel(const float* __restrict__ yp) {
    __shared__ float tp[32][33];
    int n0 = blockIdx.x * 32;
    int tx = threadIdx.x, ty = threadIdx.y;
    int tid = ty * 32 + tx;
#pragma unroll
    for (int r = 0; r < 32; r += 8)
        tp[ty + r][tx] = __ldcs(yp + (size_t)(ty + r) * NN + n0 + tx);
    ((float4*)g_yhT)[(size_t)n0 * 8 + tid] = make_float4(0.f, 0.f, 0.f, 0.f);
    if (blockIdx.x == 0)
        for (int i = tid; i < 5 * BS; i += 256) g_acc[i] = 0.0;
    __syncthreads();
#pragma unroll
    for (int r = 0; r < 32; r += 8)
        g_ypT[(size_t)(n0 + ty + r) * 32 + tx] = tp[tx][ty + r];
}

// ---- per-chunk scatter: Yhat_c[:, r] += v * yp_c[:, c]   (L2-capped)
__global__ void scatter_chunk(const float* __restrict__ vals,
                              const int* __restrict__ rows,
                              const int* __restrict__ cols) {
    const float4* yp4 = (const float4*)g_ypT;
    float4*       yh4 = (float4*)g_yhT;
    int gid    = blockIdx.x * blockDim.x + threadIdx.x;
    int stride = gridDim.x * blockDim.x;
    int sub    = gid & 7;
    for (int q = gid >> 3; q < NNZ_TOT; q += (stride >> 3)) {
        int   r = __ldcs(rows + q);
        int   c = __ldcs(cols + q);
        float v = __ldcs(vals + q);
        float4 p = __ldg(&yp4[(size_t)c * 8 + sub]);
        atomicAdd(&yh4[(size_t)r * 8 + sub],
                  make_float4(v * p.x, v * p.y, v * p.z, v * p.w));
    }
}

// ---- fused reduce(c) + in-place prep(c+1).
// Phase A: yt tile -> smem, compute s1..s5 (p/h from L2-resident ypT/yhT),
//          zero yhT rows for the next scatter.
// Phase B (if has_prep): transpose next chunk's yp into THE SAME ypT rows
//          this block owns (read-before-write within the block; no cross-
//          block hazard; ypT lines stay hot in L2).
// grid = NN/128 = 2048, block = 256 (8 warps).
__global__ void reduce_prep(const float* __restrict__ yt,
                            const float* __restrict__ yp,
                            int b0, int has_prep) {
    __shared__ float smT[128][33];
    __shared__ float red[5][8][32];
    int tid  = threadIdx.x;
    int lane = tid & 31;
    int w    = tid >> 5;

    // --- Phase A1: yt tile (128 n x 32 b), transposed into smem.
    {
        int j  = tid >> 3;
        int c0 = tid & 7;
        const float4* ytr = (const float4*)(yt + (size_t)(b0 + j) * NN) + blockIdx.x * 32;
#pragma unroll
        for (int pass = 0; pass < 4; pass++) {
            int n4 = pass * 8 + c0;
            float4 v = __ldcs(&ytr[n4]);
            smT[n4 * 4 + 0][j] = v.x;
            smT[n4 * 4 + 1][j] = v.y;
            smT[n4 * 4 + 2][j] = v.z;
            smT[n4 * 4 + 3][j] = v.w;
        }
    }
    __syncthreads();

    const float4* yp4 = (const float4*)g_ypT;
    float4*       yh4 = (float4*)g_yhT;

    int j0   = (lane & 7) * 4;
    int nsub = lane >> 3;

    float a1[4] = {0, 0, 0, 0}, a2[4] = {0, 0, 0, 0}, a3[4] = {0, 0, 0, 0};
    float a4[4] = {0, 0, 0, 0}, a5[4] = {0, 0, 0, 0};

    // --- Phase A2: compute over this block's 128 rows.
#pragma unroll
    for (int k2 = 0; k2 < 4; k2++) {
        int rg_l = w * 4 + k2;                       // local row-group 0..31
        size_t f = ((size_t)blockIdx.x * 32 + rg_l) * 32 + lane;
        float4 p = __ldg(&yp4[f]);
        float4 h = yh4[f];
        yh4[f] = make_float4(0.f, 0.f, 0.f, 0.f);    // zero for next scatter
        int nl = rg_l * 4 + nsub;
        float t0 = smT[nl][j0 + 0];
        float t1 = smT[nl][j0 + 1];
        float t2 = smT[nl][j0 + 2];
        float t3 = smT[nl][j0 + 3];
        a1[0] += t0 * p.x; a1[1] += t1 * p.y; a1[2] += t2 * p.z; a1[3] += t3 * p.w;
        a2[0] += p.x * h.x; a2[1] += p.y * h.y; a2[2] += p.z * h.z; a2[3] += p.w * h.w;
        a3[0] += t0 * t0;  a3[1] += t1 * t1;  a3[2] += t2 * t2;  a3[3] += t3 * t3;
        a4[0] += t0 * h.x; a4[1] += t1 * h.y; a4[2] += t2 * h.z; a4[3] += t3 * h.w;
        a5[0] += h.x * h.x; a5[1] += h.y * h.y; a5[2] += h.z * h.z; a5[3] += h.w * h.w;
    }

    // lanes {l, l+8, l+16, l+24} hold the same 4 batch columns
#pragma unroll
    for (int k = 0; k < 4; k++) {
#pragma unroll
        for (int d = 16; d >= 8; d >>= 1) {
            a1[k] += __shfl_down_sync(0xffffffffu, a1[k], d);
            a2[k] += __shfl_down_sync(0xffffffffu, a2[k], d);
            a3[k] += __shfl_down_sync(0xffffffffu, a3[k], d);
            a4[k] += __shfl_down_sync(0xffffffffu, a4[k], d);
            a5[k] += __shfl_down_sync(0xffffffffu, a5[k], d);
        }
    }

    if (lane < 8) {
#pragma unroll
        for (int k = 0; k < 4; k++) {
            red[0][w][lane * 4 + k] = a1[k];
            red[1][w][lane * 4 + k] = a2[k];
            red[2][w][lane * 4 + k] = a3[k];
            red[3][w][lane * 4 + k] = a4[k];
            red[4][w][lane * 4 + k] = a5[k];
        }
    }
    __syncthreads();

    if (tid < 160) {
        int acc = tid >> 5;
        int j   = tid & 31;
        float s = 0.f;
#pragma unroll
        for (int ww = 0; ww < 8; ww++) s += red[acc][ww][j];
        atomicAdd(&g_acc[acc * BS + b0 + j], (double)s);
    }

    // --- Phase B: in-place prep of next chunk into this block's ypT rows.
    if (has_prep) {
        int b0n = b0 + CH;
        // load yp(next) tile (128 n x 32 b) transposed into smT
        {
            int j  = tid >> 3;
            int c0 = tid & 7;
            const float4* ypr = (const float4*)(yp + (size_t)(b0n + j) * NN) + blockIdx.x * 32;
#pragma unroll
            for (int pass = 0; pass < 4; pass++) {
                int n4 = pass * 8 + c0;
                float4 v = __ldcs(&ypr[n4]);
                smT[n4 * 4 + 0][j] = v.x;
                smT[n4 * 4 + 1][j] = v.y;
                smT[n4 * 4 + 2][j] = v.z;
                smT[n4 * 4 + 3][j] = v.w;
            }
        }
        __syncthreads();
        // write out: coalesced 128 B per warp-row, conflict-free smem reads
        int tx = tid & 31, ty = tid >> 5;     // 32 x 8
        size_t nbase = (size_t)blockIdx.x * 128;
#pragma unroll
        for (int r = 0; r < 128; r += 8)
            g_ypT[(nbase + ty + r) * 32 + tx] = smT[ty + r][tx];
    }
}

// ------------------------------------------------------------ final scalar
__global__ void final_kernel(float* out) {
    int b = threadIdx.x;            // 128 threads
    double s1 = g_acc[0 * BS + b];
    double s2 = g_acc[1 * BS + b];
    double s3 = g_acc[2 * BS + b];
    double s4 = g_acc[3 * BS + b];
    double s5 = g_acc[4 * BS + b];
    double c  = s1 / s2;
    double r  = s3 - 2.0 * c * s4 + c * c * s5;
    __shared__ double sh[128];
    sh[b] = r;
    __syncthreads();
    for (int s = 64; s > 0; s >>= 1) {
        if (b < s) sh[b] += sh[b + s];
        __syncthreads();
    }
    if (b == 0) out[0] = (float)(sh[0] / (double)BS);
}

extern "C" void kernel_launch(void* const* d_in, const int* in_sizes, int n_in,
                              void* d_out, int out_size) {
    const float* yp   = (const float*)d_in[0];
    const float* yt   = (const float*)d_in[1];
    const float* vals = (const float*)d_in[2];
    const int*   rows = (const int*)d_in[3];
    const int*   cols = (const int*)d_in[4];
    float*       out  = (float*)d_out;

    init_kernel<<<NN / 32, dim3(32, 8)>>>(yp);
    for (int c = 0; c < NCHUNK; c++) {
        scatter_chunk<<<2368, 256>>>(vals, rows, cols);
        reduce_prep<<<NN / 128, 256>>>(yt, yp, c * CH, c < NCHUNK - 1);
    }
    final_kernel<<<1, BS>>>(out);
}